// round 15
// baseline (speedup 1.0000x reference)
#include <cuda_runtime.h>
#include <cuda_fp16.h>
#include <math.h>

#define N_NODES   100000
#define N_EDGES   6400000
#define N_FEAT    128
#define HIDDEN    16
#define N_CLASSES 10
#define N_GRAPHS  1024
#define FULL      0xffffffffu
#define MAXD      160          // ELL width; P(deg>=160 | Poisson(64)) ~ 1e-18

// ---------------- scratch (device globals; no allocation allowed) ------------
__device__ int   g_pos[N_NODES];                       // insertion cursor -> degree
__device__ int   g_ell[(size_t)N_NODES * MAXD];        // ELL neighbor table (64 MB)
__device__ __align__(16) __half g_h0[(size_t)N_NODES * HIDDEN];
__device__ __align__(16) __half g_h1[(size_t)N_NODES * HIDDEN];
__device__ __align__(16) __half g_h2[(size_t)N_NODES * HIDDEN];
__device__ float g_pooled[N_GRAPHS * N_CLASSES];
__device__ float g_cnt[N_GRAPHS];

// ---------------- 0) init -------------------------------------------------------
__global__ void k_init() {
    int i = blockIdx.x * blockDim.x + threadIdx.x;
    if (i < N_NODES) g_pos[i] = 0;
    if (i < N_GRAPHS * N_CLASSES) g_pooled[i] = 0.0f;
    if (i < N_GRAPHS) g_cnt[i] = 0.0f;
}

// ---------------- 1) argmax + embed: h0[node] = half(emb[argmax(x[node])]) -----
__global__ void k_argmax_embed(const float* __restrict__ x,
                               const float* __restrict__ emb) {
    int warp = (blockIdx.x * blockDim.x + threadIdx.x) >> 5;
    int lane = threadIdx.x & 31;
    if (warp >= N_NODES) return;

    const float4* xp = reinterpret_cast<const float4*>(x + (size_t)warp * N_FEAT);
    float4 v = xp[lane];
    float best = v.x; int bi = lane * 4;
    if (v.y > best) { best = v.y; bi = lane * 4 + 1; }
    if (v.z > best) { best = v.z; bi = lane * 4 + 2; }
    if (v.w > best) { best = v.w; bi = lane * 4 + 3; }

    #pragma unroll
    for (int o = 16; o > 0; o >>= 1) {
        float ov = __shfl_down_sync(FULL, best, o);
        int   oi = __shfl_down_sync(FULL, bi,   o);
        if (ov > best || (ov == best && oi < bi)) { best = ov; bi = oi; }
    }
    bi = __shfl_sync(FULL, bi, 0);
    if (lane < HIDDEN)
        g_h0[(size_t)warp * HIDDEN + lane] = __float2half(__ldg(&emb[bi * HIDDEN + lane]));
}

// ---------------- 2) ELL build: 4 edges/thread ----------------------------------
__global__ void k_build4(const int4* __restrict__ src4, const int4* __restrict__ dst4) {
    int t = blockIdx.x * blockDim.x + threadIdx.x;
    if (t >= N_EDGES / 4) return;
    int4 s = __ldg(&src4[t]);
    int4 d = __ldg(&dst4[t]);

    int p0 = atomicAdd(&g_pos[d.x], 1);
    int p1 = atomicAdd(&g_pos[d.y], 1);
    int p2 = atomicAdd(&g_pos[d.z], 1);
    int p3 = atomicAdd(&g_pos[d.w], 1);

    __stcg(&g_ell[(size_t)d.x * MAXD + p0], s.x);
    __stcg(&g_ell[(size_t)d.y * MAXD + p1], s.y);
    __stcg(&g_ell[(size_t)d.z * MAXD + p2], s.z);
    __stcg(&g_ell[(size_t)d.w * MAXD + p3], s.w);
}

// ---------------- 3) fused SAGE conv (pull; fp16 rows; 4-row hadd2 tree) --------
// in_sel: 0->g_h0, 1->g_h1, 2->g_h2
// FUSE_POOL=false: write half row to out (1->g_h1, 2->g_h2)
// FUSE_POOL=true : atomically accumulate into g_pooled[batch[node]]
template<int HOUT, bool RELU, bool FUSE_POOL>
__launch_bounds__(256)
__global__ void k_conv(const float* __restrict__ Wl, const float* __restrict__ bb,
                       const float* __restrict__ Wr, const int* __restrict__ batch,
                       int in_sel, int out_sel) {
    __shared__ float sWl[HOUT][HIDDEN + 1];
    __shared__ float sWr[HOUT][HIDDEN + 1];
    __shared__ float sb[HOUT];
    __shared__ float sv[8][36];   // per warp: [0:16) agg sum, [16:32) self row

    int tid = threadIdx.x;
    for (int t = tid; t < HOUT * HIDDEN; t += 256) {
        sWl[t / HIDDEN][t % HIDDEN] = Wl[t];
        sWr[t / HIDDEN][t % HIDDEN] = Wr[t];
    }
    if (tid < HOUT) sb[tid] = bb[tid];
    __syncthreads();

    int warp = tid >> 5, lane = tid & 31;
    int node = blockIdx.x * 8 + warp;
    if (node >= N_NODES) return;

    const __half* h_in = (in_sel == 0) ? g_h0 : (in_sel == 1) ? g_h1 : g_h2;
    const uint4* rows = reinterpret_cast<const uint4*>(h_in);   // 2 uint4 per row

    const int* nbrs = g_ell + (size_t)node * MAXD;
    int cnt = g_pos[node];

    int q = lane & 1;    // half-row slot (8 channels = 16 B)
    int g = lane >> 1;   // neighbor group 0..15

    // self row load issued early
    uint4 self_raw = __ldg(rows + (size_t)node * 2 + q);

    float acc[8];
    #pragma unroll
    for (int j = 0; j < 8; j++) acc[j] = 0.0f;

    const uint4 zero4 = make_uint4(0u, 0u, 0u, 0u);
    for (int i = g; i < cnt; i += 64) {
        bool hB = (i + 16) < cnt, hC = (i + 32) < cnt, hD = (i + 48) < cnt;
        int sA = __ldg(&nbrs[i]);
        int sB = hB ? __ldg(&nbrs[i + 16]) : 0;
        int sC = hC ? __ldg(&nbrs[i + 32]) : 0;
        int sD = hD ? __ldg(&nbrs[i + 48]) : 0;
        uint4 rA = __ldg(rows + (size_t)sA * 2 + q);
        uint4 rB = hB ? __ldg(rows + (size_t)sB * 2 + q) : zero4;
        uint4 rC = hC ? __ldg(rows + (size_t)sC * 2 + q) : zero4;
        uint4 rD = hD ? __ldg(rows + (size_t)sD * 2 + q) : zero4;

        const __half2* ha = reinterpret_cast<const __half2*>(&rA);
        const __half2* hb = reinterpret_cast<const __half2*>(&rB);
        const __half2* hc = reinterpret_cast<const __half2*>(&rC);
        const __half2* hd = reinterpret_cast<const __half2*>(&rD);
        #pragma unroll
        for (int k = 0; k < 4; k++) {
            __half2 p = __hadd2(__hadd2(ha[k], hb[k]), __hadd2(hc[k], hd[k]));
            float2 f = __half22float2(p);
            acc[k * 2 + 0] += f.x;
            acc[k * 2 + 1] += f.y;
        }
    }

    // reduce across the 16 groups (xor offsets keep q = bit0 fixed)
    #pragma unroll
    for (int off = 2; off < 32; off <<= 1) {
        #pragma unroll
        for (int j = 0; j < 8; j++)
            acc[j] += __shfl_xor_sync(FULL, acc[j], off);
    }

    if (lane < 2) {
        #pragma unroll
        for (int j = 0; j < 8; j++)
            sv[warp][lane * 8 + j] = acc[j];
        const __half2* hp = reinterpret_cast<const __half2*>(&self_raw);
        #pragma unroll
        for (int k = 0; k < 4; k++) {
            float2 f = __half22float2(hp[k]);
            sv[warp][16 + lane * 8 + k * 2 + 0] = f.x;
            sv[warp][16 + lane * 8 + k * 2 + 1] = f.y;
        }
    }
    __syncwarp();

    float inv = 1.0f / fmaxf((float)cnt, 1.0f);

    float o = 0.0f;
    if (lane < HOUT) {
        o = sb[lane];
        #pragma unroll
        for (int j = 0; j < HIDDEN; j++)
            o = fmaf(sv[warp][j] * inv, sWl[lane][j], fmaf(sv[warp][16 + j], sWr[lane][j], o));
    }
    float nsq = (lane < HOUT) ? o * o : 0.0f;
    #pragma unroll
    for (int off = 16; off > 0; off >>= 1)
        nsq += __shfl_xor_sync(FULL, nsq, off);
    float invn = 1.0f / fmaxf(sqrtf(nsq), 1e-12f);

    if (FUSE_POOL) {
        if (lane < HOUT) {
            int grp = __ldg(&batch[node]);
            atomicAdd(&g_pooled[grp * N_CLASSES + lane], o * invn);
        }
        if (lane == 0) {
            int grp = __ldg(&batch[node]);
            atomicAdd(&g_cnt[grp], 1.0f);
        }
    } else {
        if (lane < HOUT) {
            float v = o * invn;
            if (RELU) v = fmaxf(v, 0.0f);
            __half* outp = (out_sel == 1) ? g_h1 : g_h2;
            outp[(size_t)node * HOUT + lane] = __float2half(v);
        }
    }
}

// ---------------- 4) mean + softmax --------------------------------------------
__global__ void k_softmax(float* __restrict__ out) {
    int g = blockIdx.x * blockDim.x + threadIdx.x;
    if (g >= N_GRAPHS) return;
    float inv = 1.0f / fmaxf(g_cnt[g], 1.0f);
    float v[N_CLASSES];
    float mx = -INFINITY;
    #pragma unroll
    for (int c = 0; c < N_CLASSES; c++) {
        v[c] = g_pooled[g * N_CLASSES + c] * inv;
        mx = fmaxf(mx, v[c]);
    }
    float s = 0.0f;
    #pragma unroll
    for (int c = 0; c < N_CLASSES; c++) { v[c] = expf(v[c] - mx); s += v[c]; }
    float inv_s = 1.0f / s;
    #pragma unroll
    for (int c = 0; c < N_CLASSES; c++)
        out[g * N_CLASSES + c] = v[c] * inv_s;
}

// ---------------- launch ---------------------------------------------------------
extern "C" void kernel_launch(void* const* d_in, const int* in_sizes, int n_in,
                              void* d_out, int out_size) {
    const float* x     = (const float*)d_in[0];
    const int*   ei    = (const int*)d_in[1];   // [2, E] int32
    const int*   batch = (const int*)d_in[2];
    const float* emb   = (const float*)d_in[3];
    const float* W1l   = (const float*)d_in[4];
    const float* b1    = (const float*)d_in[5];
    const float* W1r   = (const float*)d_in[6];
    const float* W2l   = (const float*)d_in[7];
    const float* b2    = (const float*)d_in[8];
    const float* W2r   = (const float*)d_in[9];
    const float* W3l   = (const float*)d_in[10];
    const float* b3    = (const float*)d_in[11];
    const float* W3r   = (const float*)d_in[12];
    float* out = (float*)d_out;

    const int4* src4 = (const int4*)ei;
    const int4* dst4 = (const int4*)(ei + N_EDGES);

    const int TB = 256;
    const int gb_node  = (N_NODES + TB - 1) / TB;
    const int gb_edge4 = (N_EDGES / 4 + TB - 1) / TB;
    const int gb_warp  = (N_NODES * 32 + TB - 1) / TB;
    const int gb_conv  = (N_NODES + 7) / 8;

    k_init<<<gb_node, TB>>>();
    k_argmax_embed<<<gb_warp, TB>>>(x, emb);

    // ELL build (4 edges per thread)
    k_build4<<<gb_edge4, TB>>>(src4, dst4);

    // convs: h0 -> h1 -> h2 -> pooled (conv3 fuses pooling)
    k_conv<HIDDEN, true,  false><<<gb_conv, TB>>>(W1l, b1, W1r, batch, /*in*/0, /*out*/1);
    k_conv<HIDDEN, true,  false><<<gb_conv, TB>>>(W2l, b2, W2r, batch, /*in*/1, /*out*/2);
    k_conv<N_CLASSES, false, true><<<gb_conv, TB>>>(W3l, b3, W3r, batch, /*in*/2, /*out*/0);

    // softmax
    k_softmax<<<(N_GRAPHS + TB - 1) / TB, TB>>>(out);
}

// round 16
// speedup vs baseline: 1.0389x; 1.0389x over previous
#include <cuda_runtime.h>
#include <cuda_fp16.h>
#include <math.h>

#define N_NODES   100000
#define N_EDGES   6400000
#define N_FEAT    128
#define HIDDEN    16
#define N_CLASSES 10
#define N_GRAPHS  1024
#define FULL      0xffffffffu
#define MAXD      160          // ELL width; P(deg>=160 | Poisson(64)) ~ 1e-18

// ---------------- scratch (device globals; no allocation allowed) ------------
__device__ int   g_pos[N_NODES];                       // insertion cursor -> degree
__device__ int   g_ell[(size_t)N_NODES * MAXD];        // ELL neighbor table (64 MB)
__device__ __align__(16) __half g_h0[(size_t)N_NODES * HIDDEN];
__device__ __align__(16) __half g_h1[(size_t)N_NODES * HIDDEN];
__device__ __align__(16) __half g_h2[(size_t)N_NODES * HIDDEN];
__device__ float g_pooled[N_GRAPHS * N_CLASSES];
__device__ float g_cnt[N_GRAPHS];

// ---------------- 1) argmax + embed + init (folded) -----------------------------
// grid = ceil(N_NODES*32/256) = 12500 blocks; blocks cover all zeroing work too.
__global__ void k_argmax_embed(const float* __restrict__ x,
                               const float* __restrict__ emb) {
    int gtid = blockIdx.x * blockDim.x + threadIdx.x;

    // folded init (completes before any consumer kernel launches)
    if (gtid < N_NODES) g_pos[gtid] = 0;
    if (gtid < N_GRAPHS * N_CLASSES) g_pooled[gtid] = 0.0f;
    if (gtid < N_GRAPHS) g_cnt[gtid] = 0.0f;

    int warp = gtid >> 5;
    int lane = threadIdx.x & 31;
    if (warp >= N_NODES) return;

    const float4* xp = reinterpret_cast<const float4*>(x + (size_t)warp * N_FEAT);
    float4 v = xp[lane];
    float best = v.x; int bi = lane * 4;
    if (v.y > best) { best = v.y; bi = lane * 4 + 1; }
    if (v.z > best) { best = v.z; bi = lane * 4 + 2; }
    if (v.w > best) { best = v.w; bi = lane * 4 + 3; }

    #pragma unroll
    for (int o = 16; o > 0; o >>= 1) {
        float ov = __shfl_down_sync(FULL, best, o);
        int   oi = __shfl_down_sync(FULL, bi,   o);
        if (ov > best || (ov == best && oi < bi)) { best = ov; bi = oi; }
    }
    bi = __shfl_sync(FULL, bi, 0);
    if (lane < HIDDEN)
        g_h0[(size_t)warp * HIDDEN + lane] = __float2half(__ldg(&emb[bi * HIDDEN + lane]));
}

// ---------------- 2) ELL build: 4 edges/thread ----------------------------------
__global__ void k_build4(const int4* __restrict__ src4, const int4* __restrict__ dst4) {
    int t = blockIdx.x * blockDim.x + threadIdx.x;
    if (t >= N_EDGES / 4) return;
    int4 s = __ldg(&src4[t]);
    int4 d = __ldg(&dst4[t]);

    int p0 = atomicAdd(&g_pos[d.x], 1);
    int p1 = atomicAdd(&g_pos[d.y], 1);
    int p2 = atomicAdd(&g_pos[d.z], 1);
    int p3 = atomicAdd(&g_pos[d.w], 1);

    __stcg(&g_ell[(size_t)d.x * MAXD + p0], s.x);
    __stcg(&g_ell[(size_t)d.y * MAXD + p1], s.y);
    __stcg(&g_ell[(size_t)d.z * MAXD + p2], s.z);
    __stcg(&g_ell[(size_t)d.w * MAXD + p3], s.w);
}

// ---------------- 3) fused SAGE conv (R11-exact: fp16 rows, hadd2 pairs) --------
// in_sel: 0->g_h0, 1->g_h1, 2->g_h2
// FUSE_POOL=false: write half row to out (1->g_h1, 2->g_h2)
// FUSE_POOL=true : atomically accumulate into g_pooled[batch[node]]
template<int HOUT, bool RELU, bool FUSE_POOL>
__launch_bounds__(256)
__global__ void k_conv(const float* __restrict__ Wl, const float* __restrict__ bb,
                       const float* __restrict__ Wr, const int* __restrict__ batch,
                       int in_sel, int out_sel) {
    __shared__ float sWl[HOUT][HIDDEN + 1];
    __shared__ float sWr[HOUT][HIDDEN + 1];
    __shared__ float sb[HOUT];
    __shared__ float sv[8][36];   // per warp: [0:16) agg sum, [16:32) self row

    int tid = threadIdx.x;
    for (int t = tid; t < HOUT * HIDDEN; t += 256) {
        sWl[t / HIDDEN][t % HIDDEN] = Wl[t];
        sWr[t / HIDDEN][t % HIDDEN] = Wr[t];
    }
    if (tid < HOUT) sb[tid] = bb[tid];
    __syncthreads();

    int warp = tid >> 5, lane = tid & 31;
    int node = blockIdx.x * 8 + warp;
    if (node >= N_NODES) return;

    const __half* h_in = (in_sel == 0) ? g_h0 : (in_sel == 1) ? g_h1 : g_h2;
    const uint4* rows = reinterpret_cast<const uint4*>(h_in);   // 2 uint4 per row

    const int* nbrs = g_ell + (size_t)node * MAXD;
    int cnt = g_pos[node];

    int q = lane & 1;    // half-row slot (8 channels = 16 B)
    int g = lane >> 1;   // neighbor group 0..15

    // self row load issued early
    uint4 self_raw = __ldg(rows + (size_t)node * 2 + q);

    float acc[8];
    #pragma unroll
    for (int j = 0; j < 8; j++) acc[j] = 0.0f;

    const uint4 zero4 = make_uint4(0u, 0u, 0u, 0u);
    for (int i = g; i < cnt; i += 32) {
        int sA = __ldg(&nbrs[i]);
        bool hasB = (i + 16) < cnt;
        int sB = hasB ? __ldg(&nbrs[i + 16]) : 0;
        uint4 rA = __ldg(rows + (size_t)sA * 2 + q);
        uint4 rB = hasB ? __ldg(rows + (size_t)sB * 2 + q) : zero4;

        const __half2* ha = reinterpret_cast<const __half2*>(&rA);
        const __half2* hb = reinterpret_cast<const __half2*>(&rB);
        #pragma unroll
        for (int k = 0; k < 4; k++) {
            __half2 p = __hadd2(ha[k], hb[k]);     // fp16 pair add
            float2 f = __half22float2(p);
            acc[k * 2 + 0] += f.x;
            acc[k * 2 + 1] += f.y;
        }
    }

    // reduce across the 16 groups (xor offsets keep q = bit0 fixed)
    #pragma unroll
    for (int off = 2; off < 32; off <<= 1) {
        #pragma unroll
        for (int j = 0; j < 8; j++)
            acc[j] += __shfl_xor_sync(FULL, acc[j], off);
    }

    if (lane < 2) {
        #pragma unroll
        for (int j = 0; j < 8; j++)
            sv[warp][lane * 8 + j] = acc[j];
        const __half2* hp = reinterpret_cast<const __half2*>(&self_raw);
        #pragma unroll
        for (int k = 0; k < 4; k++) {
            float2 f = __half22float2(hp[k]);
            sv[warp][16 + lane * 8 + k * 2 + 0] = f.x;
            sv[warp][16 + lane * 8 + k * 2 + 1] = f.y;
        }
    }
    __syncwarp();

    float inv = 1.0f / fmaxf((float)cnt, 1.0f);

    float o = 0.0f;
    if (lane < HOUT) {
        o = sb[lane];
        #pragma unroll
        for (int j = 0; j < HIDDEN; j++)
            o = fmaf(sv[warp][j] * inv, sWl[lane][j], fmaf(sv[warp][16 + j], sWr[lane][j], o));
    }
    float nsq = (lane < HOUT) ? o * o : 0.0f;
    #pragma unroll
    for (int off = 16; off > 0; off >>= 1)
        nsq += __shfl_xor_sync(FULL, nsq, off);
    float invn = 1.0f / fmaxf(sqrtf(nsq), 1e-12f);

    if (FUSE_POOL) {
        if (lane < HOUT) {
            int grp = __ldg(&batch[node]);
            atomicAdd(&g_pooled[grp * N_CLASSES + lane], o * invn);
        }
        if (lane == 0) {
            int grp = __ldg(&batch[node]);
            atomicAdd(&g_cnt[grp], 1.0f);
        }
    } else {
        if (lane < HOUT) {
            float v = o * invn;
            if (RELU) v = fmaxf(v, 0.0f);
            __half* outp = (out_sel == 1) ? g_h1 : g_h2;
            outp[(size_t)node * HOUT + lane] = __float2half(v);
        }
    }
}

// ---------------- 4) mean + softmax --------------------------------------------
__global__ void k_softmax(float* __restrict__ out) {
    int g = blockIdx.x * blockDim.x + threadIdx.x;
    if (g >= N_GRAPHS) return;
    float inv = 1.0f / fmaxf(g_cnt[g], 1.0f);
    float v[N_CLASSES];
    float mx = -INFINITY;
    #pragma unroll
    for (int c = 0; c < N_CLASSES; c++) {
        v[c] = g_pooled[g * N_CLASSES + c] * inv;
        mx = fmaxf(mx, v[c]);
    }
    float s = 0.0f;
    #pragma unroll
    for (int c = 0; c < N_CLASSES; c++) { v[c] = expf(v[c] - mx); s += v[c]; }
    float inv_s = 1.0f / s;
    #pragma unroll
    for (int c = 0; c < N_CLASSES; c++)
        out[g * N_CLASSES + c] = v[c] * inv_s;
}

// ---------------- launch ---------------------------------------------------------
extern "C" void kernel_launch(void* const* d_in, const int* in_sizes, int n_in,
                              void* d_out, int out_size) {
    const float* x     = (const float*)d_in[0];
    const int*   ei    = (const int*)d_in[1];   // [2, E] int32
    const int*   batch = (const int*)d_in[2];
    const float* emb   = (const float*)d_in[3];
    const float* W1l   = (const float*)d_in[4];
    const float* b1    = (const float*)d_in[5];
    const float* W1r   = (const float*)d_in[6];
    const float* W2l   = (const float*)d_in[7];
    const float* b2    = (const float*)d_in[8];
    const float* W2r   = (const float*)d_in[9];
    const float* W3l   = (const float*)d_in[10];
    const float* b3    = (const float*)d_in[11];
    const float* W3r   = (const float*)d_in[12];
    float* out = (float*)d_out;

    const int4* src4 = (const int4*)ei;
    const int4* dst4 = (const int4*)(ei + N_EDGES);

    const int TB = 256;
    const int gb_edge4 = (N_EDGES / 4 + TB - 1) / TB;
    const int gb_warp  = (N_NODES * 32 + TB - 1) / TB;
    const int gb_conv  = (N_NODES + 7) / 8;

    // argmax + embed + zero-init (folded)
    k_argmax_embed<<<gb_warp, TB>>>(x, emb);

    // ELL build (4 edges per thread)
    k_build4<<<gb_edge4, TB>>>(src4, dst4);

    // convs: h0 -> h1 -> h2 -> pooled (conv3 fuses pooling)
    k_conv<HIDDEN, true,  false><<<gb_conv, TB>>>(W1l, b1, W1r, batch, /*in*/0, /*out*/1);
    k_conv<HIDDEN, true,  false><<<gb_conv, TB>>>(W2l, b2, W2r, batch, /*in*/1, /*out*/2);
    k_conv<N_CLASSES, false, true><<<gb_conv, TB>>>(W3l, b3, W3r, batch, /*in*/2, /*out*/0);

    // softmax
    k_softmax<<<(N_GRAPHS + TB - 1) / TB, TB>>>(out);
}